// round 7
// baseline (speedup 1.0000x reference)
#include <cuda_runtime.h>
#include <math.h>

// ---------------------------------------------------------------------------
// SlotAttention: b=32, n=1024, c=256, d=256, S=8 slots, 3 iters.
// LN folded into GEMM epilogues; KV fused tf32 mma; fused attention kernel;
// register-double-buffered small GEMMs.
// ---------------------------------------------------------------------------
#define Bsz 32
#define NTOK 1024
#define NSLOT 8
#define ITERS 3
#define TOKROWS (Bsz*NTOK)      // 32768
#define SROWS (Bsz*NSLOT)       // 256
#define SCALE_F 0.0625f
#define EPS_F 1e-8f
#define NCHUNK 8                // attn j-chunks of 128

// scratch arena (floats)
#define OFF_KV     0                                  // 32768*512
#define OFF_SLOTS  (OFF_KV + TOKROWS*512)             // 256*256
#define OFF_GBUF   (OFF_SLOTS + SROWS*256)
#define OFF_U      (OFF_GBUF + SROWS*256)
#define OFF_H1     (OFF_U + SROWS*256)                // 256*1024
#define OFF_UPDP   (OFF_H1 + SROWS*1024)              // 8*256*256
#define OFF_RSP    (OFF_UPDP + NCHUNK*SROWS*256)      // 8*256
#define OFF_WKV    (OFF_RSP + NCHUNK*SROWS)           // 512*256
#define OFF_S1KV   (OFF_WKV + 512*256)                // 512
#define OFF_S2KV   (OFF_S1KV + 512)
#define OFF_WQT    (OFF_S2KV + 512)                   // 256*256
#define OFF_S1Q    (OFF_WQT + 256*256)
#define OFF_S2Q    (OFF_S1Q + 256)
#define OFF_W1P    (OFF_S2Q + 256)                    // 1024*256
#define OFF_S1M    (OFF_W1P + 1024*256)
#define OFF_S2M    (OFF_S1M + 1024)
#define SCRATCH_FLOATS (OFF_S2M + 1024)

__device__ float g_scratch[SCRATCH_FLOATS];

__device__ __forceinline__ float warp_sum(float v) {
#pragma unroll
    for (int o = 16; o > 0; o >>= 1) v += __shfl_xor_sync(0xffffffffu, v, o);
    return v;
}
__device__ __forceinline__ float grp8_sum(float v) {
    v += __shfl_xor_sync(0xffffffffu, v, 4);
    v += __shfl_xor_sync(0xffffffffu, v, 2);
    v += __shfl_xor_sync(0xffffffffu, v, 1);
    return v;
}
__device__ __forceinline__ float f2tf(float x) {
    asm("cvt.rna.tf32.f32 %0, %0;" : "+f"(x));
    return x;
}
__device__ __forceinline__ void mma8(float* d, const unsigned* a, const unsigned* b) {
    asm volatile("mma.sync.aligned.m16n8k8.row.col.f32.tf32.tf32.f32 "
        "{%0,%1,%2,%3}, {%4,%5,%6,%7}, {%8,%9}, {%0,%1,%2,%3};"
        : "+f"(d[0]), "+f"(d[1]), "+f"(d[2]), "+f"(d[3])
        : "r"(a[0]), "r"(a[1]), "r"(a[2]), "r"(a[3]), "r"(b[0]), "r"(b[1]));
}
__device__ __forceinline__ float sigmoidf_(float x) { return 1.0f / (1.0f + __expf(-x)); }

// ---------------------------------------------------------------------------
// prep: W'kv (stacked Wk;Wv, g-scaled, tf32-rounded) + S1/S2
// ---------------------------------------------------------------------------
__global__ void prep_kv_kernel(const float* __restrict__ Wk, const float* __restrict__ Wv,
                               const float* __restrict__ g, const float* __restrict__ b,
                               float* __restrict__ Wp, float* __restrict__ S1, float* __restrict__ S2) {
    int w = threadIdx.x >> 5, lane = threadIdx.x & 31;
    int n = blockIdx.x * 8 + w;
    const float* src = (n < 256) ? Wk + (size_t)n * 256 : Wv + (size_t)(n - 256) * 256;
    float s1 = 0.f, s2 = 0.f;
#pragma unroll
    for (int u = 0; u < 8; u++) {
        int c = u * 32 + lane;
        float wt = f2tf(src[c] * g[c]);
        Wp[(size_t)n * 256 + c] = wt;
        s1 += wt;
        s2 += src[c] * b[c];
    }
    s1 = warp_sum(s1); s2 = warp_sum(s2);
    if (lane == 0) { S1[n] = s1; S2[n] = s2; }
}

// W'q transposed [c][n] (fp32) + S1q/S2q
__global__ void prep_q_kernel(const float* __restrict__ Wq,
                              const float* __restrict__ g, const float* __restrict__ b,
                              float* __restrict__ WqT, float* __restrict__ S1, float* __restrict__ S2) {
    int w = threadIdx.x >> 5, lane = threadIdx.x & 31;
    int n = blockIdx.x * 8 + w;
    float s1 = 0.f, s2 = 0.f;
#pragma unroll
    for (int u = 0; u < 8; u++) {
        int c = u * 32 + lane;
        float wv = Wq[(size_t)n * 256 + c] * g[c];
        WqT[(size_t)c * 256 + n] = wv;
        s1 += wv;
        s2 += Wq[(size_t)n * 256 + c] * b[c];
    }
    s1 = warp_sum(s1); s2 = warp_sum(s2);
    if (lane == 0) { S1[n] = s1; S2[n] = s2; }
}

// W'1 row-major (fp32) + S1m/S2m
__global__ void prep_m1_kernel(const float* __restrict__ W1,
                               const float* __restrict__ g, const float* __restrict__ b,
                               float* __restrict__ W1p, float* __restrict__ S1, float* __restrict__ S2) {
    int w = threadIdx.x >> 5, lane = threadIdx.x & 31;
    int n = blockIdx.x * 8 + w;
    float s1 = 0.f, s2 = 0.f;
#pragma unroll
    for (int u = 0; u < 8; u++) {
        int c = u * 32 + lane;
        float wv = W1[(size_t)n * 256 + c] * g[c];
        W1p[(size_t)n * 256 + c] = wv;
        s1 += wv;
        s2 += W1[(size_t)n * 256 + c] * b[c];
    }
    s1 = warp_sum(s1); s2 = warp_sum(s2);
    if (lane == 0) { S1[n] = s1; S2[n] = s2; }
}

__global__ void init_slots_kernel(const float* __restrict__ mu, const float* __restrict__ ls,
                                  const float* __restrict__ noise, float* __restrict__ slots) {
    int idx = blockIdx.x * blockDim.x + threadIdx.x;
    int d = idx & 255;
    slots[idx] = mu[d] + __expf(ls[d]) * noise[idx];
}

// ---------------------------------------------------------------------------
// KV GEMM: C[32768, 512] = LN(x) @ [W'k;W'v]^T via tf32 mma + LN-fold epilogue.
// BM=128 BN=128 BK=32; in-kernel streamed row stats; register double buffer.
// ---------------------------------------------------------------------------
__global__ __launch_bounds__(256) void kv_mma_kernel(
    const float* __restrict__ x, const float* __restrict__ Wp,
    const float* __restrict__ S1, const float* __restrict__ S2,
    float* __restrict__ C) {
    __shared__ float As[128][36];
    __shared__ float Bs[128][36];
    __shared__ float rowm[128], rowr[128];
    int t = threadIdx.x;
    int bm = blockIdx.y * 128, bn = blockIdx.x * 128;
    int w = t >> 5, lane = t & 31;
    int m0 = (w >> 2) * 64, n0 = (w & 3) * 32;
    int g = lane >> 2, tig = lane & 3;
    float acc[4][4][4];
#pragma unroll
    for (int a = 0; a < 4; a++)
#pragma unroll
        for (int bq = 0; bq < 4; bq++)
#pragma unroll
            for (int c = 0; c < 4; c++) acc[a][bq][c] = 0.f;

    int lm = t >> 3, lk = (t & 7) * 4;
    float4 ar[4], br[4];
    float sA[4] = {0.f, 0.f, 0.f, 0.f}, s2A[4] = {0.f, 0.f, 0.f, 0.f};
#pragma unroll
    for (int r = 0; r < 4; r++) {
        ar[r] = *(const float4*)(x + (size_t)(bm + r * 32 + lm) * 256 + lk);
        br[r] = *(const float4*)(Wp + (size_t)(bn + r * 32 + lm) * 256 + lk);
    }
    for (int it = 0; it < 8; it++) {
#pragma unroll
        for (int r = 0; r < 4; r++) {
            sA[r] += ar[r].x + ar[r].y + ar[r].z + ar[r].w;
            s2A[r] += ar[r].x * ar[r].x + ar[r].y * ar[r].y + ar[r].z * ar[r].z + ar[r].w * ar[r].w;
        }
        __syncthreads();
#pragma unroll
        for (int r = 0; r < 4; r++) {
            int m = r * 32 + lm;
            As[m][lk + 0] = f2tf(ar[r].x); As[m][lk + 1] = f2tf(ar[r].y);
            As[m][lk + 2] = f2tf(ar[r].z); As[m][lk + 3] = f2tf(ar[r].w);
            *(float4*)&Bs[m][lk] = br[r];
        }
        __syncthreads();
        if (it < 7) {
            int c = (it + 1) * 32 + lk;
#pragma unroll
            for (int r = 0; r < 4; r++) {
                ar[r] = *(const float4*)(x + (size_t)(bm + r * 32 + lm) * 256 + c);
                br[r] = *(const float4*)(Wp + (size_t)(bn + r * 32 + lm) * 256 + c);
            }
        }
#pragma unroll
        for (int ks = 0; ks < 32; ks += 8) {
            unsigned a[4][4], b[4][2];
#pragma unroll
            for (int mt = 0; mt < 4; mt++) {
                int mr = m0 + mt * 16 + g;
                a[mt][0] = __float_as_uint(As[mr][ks + tig]);
                a[mt][1] = __float_as_uint(As[mr + 8][ks + tig]);
                a[mt][2] = __float_as_uint(As[mr][ks + tig + 4]);
                a[mt][3] = __float_as_uint(As[mr + 8][ks + tig + 4]);
            }
#pragma unroll
            for (int nt = 0; nt < 4; nt++) {
                int nr = n0 + nt * 8 + g;
                b[nt][0] = __float_as_uint(Bs[nr][ks + tig]);
                b[nt][1] = __float_as_uint(Bs[nr][ks + tig + 4]);
            }
#pragma unroll
            for (int mt = 0; mt < 4; mt++)
#pragma unroll
                for (int nt = 0; nt < 4; nt++)
                    mma8(acc[mt][nt], a[mt], b[nt]);
        }
    }
    // finalize row stats (8 threads share each row)
#pragma unroll
    for (int r = 0; r < 4; r++) {
        float s = grp8_sum(sA[r]);
        float s2 = grp8_sum(s2A[r]);
        if ((t & 7) == 0) {
            float m = s * (1.0f / 256.0f);
            float var = s2 * (1.0f / 256.0f) - m * m;
            rowm[r * 32 + lm] = m;
            rowr[r * 32 + lm] = rsqrtf(var + 1e-5f);
        }
    }
    __syncthreads();
#pragma unroll
    for (int mt = 0; mt < 4; mt++)
#pragma unroll
        for (int nt = 0; nt < 4; nt++) {
            int lr = m0 + mt * 16 + g;
            int col = bn + n0 + nt * 8 + tig * 2;
            float s1a = S1[col], s1b = S1[col + 1], s2a = S2[col], s2b = S2[col + 1];
            float m0v = rowm[lr], r0v = rowr[lr];
            float m1v = rowm[lr + 8], r1v = rowr[lr + 8];
            float2 o0 = make_float2(r0v * acc[mt][nt][0] - r0v * m0v * s1a + s2a,
                                    r0v * acc[mt][nt][1] - r0v * m0v * s1b + s2b);
            float2 o1 = make_float2(r1v * acc[mt][nt][2] - r1v * m1v * s1a + s2a,
                                    r1v * acc[mt][nt][3] - r1v * m1v * s1b + s2b);
            *(float2*)(C + (size_t)(bm + lr) * 512 + col) = o0;
            *(float2*)(C + (size_t)(bm + lr + 8) * 512 + col) = o1;
        }
}

// ---------------------------------------------------------------------------
// fused attention: LN(slots)->q (via W'qT + epilogue), dots, softmax over
// slots, updates partials + rowsum partials. grid (32 batches, 8 j-chunks).
// ---------------------------------------------------------------------------
__global__ __launch_bounds__(256) void attn_fused_kernel(
    const float* __restrict__ slots, const float* __restrict__ WqT,
    const float* __restrict__ S1q, const float* __restrict__ S2q,
    const float* __restrict__ kv, float* __restrict__ updp, float* __restrict__ rsp) {
    __shared__ float sln[8][256];
    __shared__ float qs[8][256];
    __shared__ float attn_s[128][9];
    __shared__ float rm[8], rr[8], rswarp[8][8];
    int b = blockIdx.x, jc = blockIdx.y;
    int t = threadIdx.x, w = t >> 5, lane = t & 31;

    // phase 0: load slots[b], row stats (warp per slot row)
    {
        const float* srow = slots + (size_t)(b * 8 + w) * 256;
        float s = 0.f, s2 = 0.f;
#pragma unroll
        for (int u = 0; u < 8; u++) {
            float v = srow[u * 32 + lane];
            sln[w][u * 32 + lane] = v;
            s += v; s2 += v * v;
        }
        s = warp_sum(s); s2 = warp_sum(s2);
        if (lane == 0) {
            float m = s * (1.0f / 256.0f);
            float var = s2 * (1.0f / 256.0f) - m * m;
            rm[w] = m; rr[w] = rsqrtf(var + 1e-5f);
        }
    }
    __syncthreads();

    // phase 1: q[i][t] for all 8 slots (thread t = output col)
    {
        float qa[8];
#pragma unroll
        for (int i = 0; i < 8; i++) qa[i] = 0.f;
        for (int c0 = 0; c0 < 256; c0 += 4) {
            float w0 = WqT[(size_t)(c0 + 0) * 256 + t];
            float w1 = WqT[(size_t)(c0 + 1) * 256 + t];
            float w2 = WqT[(size_t)(c0 + 2) * 256 + t];
            float w3 = WqT[(size_t)(c0 + 3) * 256 + t];
#pragma unroll
            for (int i = 0; i < 8; i++) {
                float4 sv = *(const float4*)&sln[i][c0];
                qa[i] += sv.x * w0 + sv.y * w1 + sv.z * w2 + sv.w * w3;
            }
        }
        float s1 = S1q[t], s2v = S2q[t];
#pragma unroll
        for (int i = 0; i < 8; i++) {
            float qv = rr[i] * qa[i] - rr[i] * rm[i] * s1 + s2v;
            qs[i][t] = qv * SCALE_F;
        }
    }
    __syncthreads();

    // phase 2: dots + softmax over slots (warp handles 16 j's)
    float rsa = 0.f;
#pragma unroll 1
    for (int jj = 0; jj < 16; jj++) {
        int jl = w + jj * 8;
        int j = jc * 128 + jl;
        const float* krow = kv + ((size_t)b * NTOK + j) * 512;
        float kr[8];
#pragma unroll
        for (int u = 0; u < 8; u++) kr[u] = krow[u * 32 + lane];
        float dv[8];
#pragma unroll
        for (int i = 0; i < 8; i++) {
            float p = 0.f;
#pragma unroll
            for (int u = 0; u < 8; u++) p += qs[i][u * 32 + lane] * kr[u];
            dv[i] = warp_sum(p);
        }
        float mx = dv[0];
#pragma unroll
        for (int i = 1; i < 8; i++) mx = fmaxf(mx, dv[i]);
        float se = 0.f, ev[8];
#pragma unroll
        for (int i = 0; i < 8; i++) { ev[i] = __expf(dv[i] - mx); se += ev[i]; }
        float inv = 1.0f / se;
        float my = 0.f;
#pragma unroll
        for (int i = 0; i < 8; i++) {
            float a = ev[i] * inv + EPS_F;
            if (lane == i) my = a;
        }
        if (lane < 8) { attn_s[jl][lane] = my; rsa += my; }
    }
    if (lane < 8) rswarp[w][lane] = rsa;
    __syncthreads();

    // phase 3: updates partials (thread t = value col)
    {
        float uacc[8];
#pragma unroll
        for (int i = 0; i < 8; i++) uacc[i] = 0.f;
        const float* vbase = kv + ((size_t)b * NTOK + jc * 128) * 512 + 256 + t;
#pragma unroll 2
        for (int jl = 0; jl < 128; jl++) {
            float va = vbase[(size_t)jl * 512];
#pragma unroll
            for (int i = 0; i < 8; i++) uacc[i] += attn_s[jl][i] * va;
        }
#pragma unroll
        for (int i = 0; i < 8; i++)
            updp[((size_t)jc * SROWS + b * 8 + i) * 256 + t] = uacc[i];
        if (t < 8) {
            float r = 0.f;
#pragma unroll
            for (int ww = 0; ww < 8; ww++) r += rswarp[ww][t];
            rsp[jc * SROWS + b * 8 + t] = r;
        }
    }
}

// u = (sum_p updp) / (sum_p rowsum)
__global__ void reduce_u_kernel(const float* __restrict__ updp, const float* __restrict__ rsp,
                                float* __restrict__ u) {
    int idx4 = blockIdx.x * blockDim.x + threadIdx.x;  // float4 index
    int row = idx4 >> 6;
    float rs = 0.f;
#pragma unroll
    for (int p = 0; p < NCHUNK; p++) rs += rsp[p * SROWS + row];
    float inv = 1.0f / rs;
    float4 a = make_float4(0.f, 0.f, 0.f, 0.f);
#pragma unroll
    for (int p = 0; p < NCHUNK; p++) {
        float4 v = *(const float4*)(updp + (size_t)p * SROWS * 256 + (size_t)idx4 * 4);
        a.x += v.x; a.y += v.y; a.z += v.z; a.w += v.w;
    }
    a.x *= inv; a.y *= inv; a.z *= inv; a.w *= inv;
    *(float4*)(u + (size_t)idx4 * 4) = a;
}

// ---------------------------------------------------------------------------
// fused GRU: gi=u@wih^T, gh=h@whh^T (3 gates each), nonlinearity, out.
// BM=BN=32, grid (8,8), register prefetch.
// ---------------------------------------------------------------------------
__global__ __launch_bounds__(256) void gru_fused_kernel(
    const float* __restrict__ u, const float* __restrict__ slots,
    const float* __restrict__ wih, const float* __restrict__ whh,
    const float* __restrict__ bih, const float* __restrict__ bhh,
    float* __restrict__ out) {
    __shared__ float Au[32][36], Ah[32][36];
    __shared__ float Bg[6][32][36];
    int t = threadIdx.x;
    int bm = blockIdx.y * 32, bn = blockIdx.x * 32;
    float acc[6][2][2];
#pragma unroll
    for (int gb = 0; gb < 6; gb++)
#pragma unroll
        for (int i = 0; i < 2; i++)
#pragma unroll
            for (int j = 0; j < 2; j++) acc[gb][i][j] = 0.f;
    int tr = t >> 4, tc = t & 15;
    int lm = t >> 3, lk = (t & 7) * 4;

    float4 pu, ph, pw[6];
    pu = *(const float4*)(u + (size_t)(bm + lm) * 256 + lk);
    ph = *(const float4*)(slots + (size_t)(bm + lm) * 256 + lk);
#pragma unroll
    for (int gb = 0; gb < 6; gb++) {
        const float* W = (gb < 3) ? wih : whh;
        pw[gb] = *(const float4*)(W + (size_t)(bn + lm + (gb % 3) * 256) * 256 + lk);
    }
    for (int it = 0; it < 8; it++) {
        __syncthreads();
        Au[lm][lk + 0] = pu.x; Au[lm][lk + 1] = pu.y; Au[lm][lk + 2] = pu.z; Au[lm][lk + 3] = pu.w;
        Ah[lm][lk + 0] = ph.x; Ah[lm][lk + 1] = ph.y; Ah[lm][lk + 2] = ph.z; Ah[lm][lk + 3] = ph.w;
#pragma unroll
        for (int gb = 0; gb < 6; gb++) {
            Bg[gb][lm][lk + 0] = pw[gb].x; Bg[gb][lm][lk + 1] = pw[gb].y;
            Bg[gb][lm][lk + 2] = pw[gb].z; Bg[gb][lm][lk + 3] = pw[gb].w;
        }
        __syncthreads();
        if (it < 7) {
            int c = (it + 1) * 32 + lk;
            pu = *(const float4*)(u + (size_t)(bm + lm) * 256 + c);
            ph = *(const float4*)(slots + (size_t)(bm + lm) * 256 + c);
#pragma unroll
            for (int gb = 0; gb < 6; gb++) {
                const float* W = (gb < 3) ? wih : whh;
                pw[gb] = *(const float4*)(W + (size_t)(bn + lm + (gb % 3) * 256) * 256 + c);
            }
        }
#pragma unroll
        for (int kk = 0; kk < 32; kk++) {
            float2 au = *(float2*)&Au[tr * 2][0] ; // placeholder to avoid confusion
            // NOTE: A is stored [row][k]; read per-thread rows tr*2, tr*2+1 at col kk
            float a0u = Au[tr * 2][kk], a1u = Au[tr * 2 + 1][kk];
            float a0h = Ah[tr * 2][kk], a1h = Ah[tr * 2 + 1][kk];
            (void)au;
#pragma unroll
            for (int gb = 0; gb < 6; gb++) {
                float b0 = Bg[gb][tc * 2][kk], b1 = Bg[gb][tc * 2 + 1][kk];
                float x0 = (gb < 3) ? a0u : a0h;
                float x1 = (gb < 3) ? a1u : a1h;
                acc[gb][0][0] += x0 * b0; acc[gb][0][1] += x0 * b1;
                acc[gb][1][0] += x1 * b0; acc[gb][1][1] += x1 * b1;
            }
        }
    }
#pragma unroll
    for (int i = 0; i < 2; i++)
#pragma unroll
        for (int j = 0; j < 2; j++) {
            int row = bm + tr * 2 + i, col = bn + tc * 2 + j;
            float ir = acc[0][i][j] + bih[col];
            float iz = acc[1][i][j] + bih[col + 256];
            float in_ = acc[2][i][j] + bih[col + 512];
            float hr = acc[3][i][j] + bhh[col];
            float hz = acc[4][i][j] + bhh[col + 256];
            float hn = acc[5][i][j] + bhh[col + 512];
            float r = sigmoidf_(ir + hr);
            float z = sigmoidf_(iz + hz);
            float nn = tanhf(in_ + r * hn);
            float h = slots[(size_t)row * 256 + col];
            out[(size_t)row * 256 + col] = (1.0f - z) * nn + z * h;
        }
}

// ---------------------------------------------------------------------------
// small GEMM with register prefetch: C = [LN-fold](A) @ B^T (+bias, relu, +add)
// BM=BN=64, BK=32, 256 threads, 4x4/thread.
// ---------------------------------------------------------------------------
template<bool EPI_LN, bool RELU, bool ADDOUT>
__global__ __launch_bounds__(256) void gemm_small_kernel(
    const float* __restrict__ A, const float* __restrict__ B,
    const float* __restrict__ S1, const float* __restrict__ S2,
    const float* __restrict__ bias, const float* __restrict__ addsrc,
    float* __restrict__ C, int M, int N, int K) {
    __shared__ float As[32][68];
    __shared__ float Bs[32][68];
    __shared__ float rowm[64], rowr[64];
    int t = threadIdx.x;
    int bm = blockIdx.y * 64, bn = blockIdx.x * 64;
    int tr = t >> 4, tc = t & 15;
    float acc[4][4];
#pragma unroll
    for (int i = 0; i < 4; i++)
#pragma unroll
        for (int j = 0; j < 4; j++) acc[i][j] = 0.f;
    int lm = t >> 3, lk = (t & 7) * 4;

    float4 ap0, ap1, bp0, bp1;
    float sA[2] = {0.f, 0.f}, s2A[2] = {0.f, 0.f};
    ap0 = *(const float4*)(A + (size_t)(bm + lm) * K + lk);
    ap1 = *(const float4*)(A + (size_t)(bm + lm + 32) * K + lk);
    bp0 = *(const float4*)(B + (size_t)(bn + lm) * K + lk);
    bp1 = *(const float4*)(B + (size_t)(bn + lm + 32) * K + lk);
    int iters = K >> 5;
    for (int it = 0; it < iters; it++) {
        if (EPI_LN) {
            sA[0] += ap0.x + ap0.y + ap0.z + ap0.w;
            s2A[0] += ap0.x * ap0.x + ap0.y * ap0.y + ap0.z * ap0.z + ap0.w * ap0.w;
            sA[1] += ap1.x + ap1.y + ap1.z + ap1.w;
            s2A[1] += ap1.x * ap1.x + ap1.y * ap1.y + ap1.z * ap1.z + ap1.w * ap1.w;
        }
        __syncthreads();
        As[lk + 0][lm] = ap0.x; As[lk + 1][lm] = ap0.y; As[lk + 2][lm] = ap0.z; As[lk + 3][lm] = ap0.w;
        As[lk + 0][lm + 32] = ap1.x; As[lk + 1][lm + 32] = ap1.y; As[lk + 2][lm + 32] = ap1.z; As[lk + 3][lm + 32] = ap1.w;
        Bs[lk + 0][lm] = bp0.x; Bs[lk + 1][lm] = bp0.y; Bs[lk + 2][lm] = bp0.z; Bs[lk + 3][lm] = bp0.w;
        Bs[lk + 0][lm + 32] = bp1.x; Bs[lk + 1][lm + 32] = bp1.y; Bs[lk + 2][lm + 32] = bp1.z; Bs[lk + 3][lm + 32] = bp1.w;
        __syncthreads();
        if (it + 1 < iters) {
            int c = (it + 1) * 32 + lk;
            ap0 = *(const float4*)(A + (size_t)(bm + lm) * K + c);
            ap1 = *(const float4*)(A + (size_t)(bm + lm + 32) * K + c);
            bp0 = *(const float4*)(B + (size_t)(bn + lm) * K + c);
            bp1 = *(const float4*)(B + (size_t)(bn + lm + 32) * K + c);
        }
#pragma unroll
        for (int kk = 0; kk < 32; kk++) {
            float4 a4 = *(float4*)&As[kk][tr * 4];
            float4 b4 = *(float4*)&Bs[kk][tc * 4];
            float a[4] = {a4.x, a4.y, a4.z, a4.w};
            float b[4] = {b4.x, b4.y, b4.z, b4.w};
#pragma unroll
            for (int i = 0; i < 4; i++)
#pragma unroll
                for (int j = 0; j < 4; j++) acc[i][j] += a[i] * b[j];
        }
    }
    if (EPI_LN) {
#pragma unroll
        for (int r = 0; r < 2; r++) {
            float s = grp8_sum(sA[r]);
            float s2 = grp8_sum(s2A[r]);
            if ((t & 7) == 0) {
                float m = s / (float)K;
                float var = s2 / (float)K - m * m;
                rowm[r * 32 + lm] = m;
                rowr[r * 32 + lm] = rsqrtf(var + 1e-5f);
            }
        }
        __syncthreads();
    }
#pragma unroll
    for (int i = 0; i < 4; i++)
#pragma unroll
        for (int j = 0; j < 4; j++) {
            int lr = tr * 4 + i;
            int row = bm + lr, col = bn + tc * 4 + j;
            float v = acc[i][j];
            if (EPI_LN) {
                float m = rowm[lr], rs = rowr[lr];
                v = rs * v - rs * m * S1[col] + S2[col];
            }
            if (bias) v += bias[col];
            if (RELU) v = fmaxf(v, 0.f);
            if (ADDOUT) v += addsrc[(size_t)row * N + col];
            C[(size_t)row * N + col] = v;
        }
}

extern "C" void kernel_launch(void* const* d_in, const int* in_sizes, int n_in,
                              void* d_out, int out_size) {
    const float* inputs    = (const float*)d_in[0];
    const float* noise     = (const float*)d_in[1];
    const float* slots_mu  = (const float*)d_in[2];
    const float* slots_ls  = (const float*)d_in[3];
    const float* Wq        = (const float*)d_in[4];
    const float* Wk        = (const float*)d_in[5];
    const float* Wv        = (const float*)d_in[6];
    const float* gru_wih   = (const float*)d_in[7];
    const float* gru_whh   = (const float*)d_in[8];
    const float* gru_bih   = (const float*)d_in[9];
    const float* gru_bhh   = (const float*)d_in[10];
    const float* mlp_w1    = (const float*)d_in[11];
    const float* mlp_b1    = (const float*)d_in[12];
    const float* mlp_w2    = (const float*)d_in[13];
    const float* mlp_b2    = (const float*)d_in[14];
    const float* ln_in_g   = (const float*)d_in[15];
    const float* ln_in_b   = (const float*)d_in[16];
    const float* ln_s_g    = (const float*)d_in[17];
    const float* ln_s_b    = (const float*)d_in[18];
    const float* ln_ff_g   = (const float*)d_in[19];
    const float* ln_ff_b   = (const float*)d_in[20];

    float* S = nullptr;
    cudaGetSymbolAddress((void**)&S, g_scratch);
    float* kv    = S + OFF_KV;
    float* slots = S + OFF_SLOTS;
    float* gbuf  = S + OFF_GBUF;
    float* ubuf  = S + OFF_U;
    float* h1    = S + OFF_H1;
    float* updp  = S + OFF_UPDP;
    float* rsp   = S + OFF_RSP;
    float* Wkv   = S + OFF_WKV;
    float* S1kv  = S + OFF_S1KV;
    float* S2kv  = S + OFF_S2KV;
    float* WqT   = S + OFF_WQT;
    float* S1q   = S + OFF_S1Q;
    float* S2q   = S + OFF_S2Q;
    float* W1p   = S + OFF_W1P;
    float* S1m   = S + OFF_S1M;
    float* S2m   = S + OFF_S2M;

    prep_kv_kernel<<<64, 256>>>(Wk, Wv, ln_in_g, ln_in_b, Wkv, S1kv, S2kv);   // 0
    prep_q_kernel<<<32, 256>>>(Wq, ln_s_g, ln_s_b, WqT, S1q, S2q);            // 1
    prep_m1_kernel<<<128, 256>>>(mlp_w1, ln_ff_g, ln_ff_b, W1p, S1m, S2m);    // 2
    init_slots_kernel<<<256, 256>>>(slots_mu, slots_ls, noise, slots);        // 3
    kv_mma_kernel<<<dim3(4, 256), 256>>>(inputs, Wkv, S1kv, S2kv, kv);        // 4

    for (int it = 0; it < ITERS; it++) {
        attn_fused_kernel<<<dim3(32, NCHUNK), 256>>>(slots, WqT, S1q, S2q, kv, updp, rsp); // 5 on it0
        reduce_u_kernel<<<64, 256>>>(updp, rsp, ubuf);
        gru_fused_kernel<<<dim3(8, 8), 256>>>(ubuf, slots, gru_wih, gru_whh, gru_bih, gru_bhh, gbuf);
        gemm_small_kernel<true, true, false><<<dim3(16, 4), 256>>>(
            gbuf, W1p, S1m, S2m, mlp_b1, nullptr, h1, 256, 1024, 256);
        float* outp = (it == ITERS - 1) ? (float*)d_out : slots;
        gemm_small_kernel<false, false, true><<<dim3(4, 4), 256>>>(
            h1, mlp_w2, nullptr, nullptr, mlp_b2, gbuf, outp, 256, 256, 1024);
    }
}